// round 5
// baseline (speedup 1.0000x reference)
#include <cuda_runtime.h>
#include <cstdint>

#define B_   16
#define L1_  1024
#define L2_  1024
#define DIN_ 1024
#define H_   16
#define DK_  64
#define DV_  64

// ---------------- scratch (allocation-free rule: __device__ globals) ----------------
__device__ float g_Q[B_ * L1_ * H_ * DK_];   // 64 MB
__device__ float g_K[B_ * L2_ * H_ * DK_];   // 64 MB
__device__ float g_V[B_ * L2_ * H_ * DV_];   // 64 MB
__device__ unsigned char g_mask_c[B_ * L2_]; // canonical mask, 1 = masked

// ---------------- helpers ----------------
__device__ __forceinline__ unsigned f2tf(float f) {
    unsigned r;
    asm("cvt.rna.tf32.f32 %0, %1;" : "=r"(r) : "f"(f));
    return r;
}
__device__ __forceinline__ float f2tf_f(float f) { return __uint_as_float(f2tf(f)); }

__device__ __forceinline__ void mma8(float* d, const unsigned* a, unsigned b0, unsigned b1) {
    asm volatile(
        "mma.sync.aligned.m16n8k8.row.col.f32.tf32.tf32.f32 "
        "{%0,%1,%2,%3}, {%4,%5,%6,%7}, {%8,%9}, {%0,%1,%2,%3};\n"
        : "+f"(d[0]), "+f"(d[1]), "+f"(d[2]), "+f"(d[3])
        : "r"(a[0]), "r"(a[1]), "r"(a[2]), "r"(a[3]), "r"(b0), "r"(b1));
}

__device__ __forceinline__ void cpa16(float* smem, const float* g) {
    unsigned s = (unsigned)__cvta_generic_to_shared(smem);
    asm volatile("cp.async.cg.shared.global [%0], [%1], 16;\n" :: "r"(s), "l"(g));
}
#define CP_COMMIT() asm volatile("cp.async.commit_group;\n" ::: "memory")
#define CP_WAIT(N)  asm volatile("cp.async.wait_group %0;\n" :: "n"(N) : "memory")

// ---------------- mask canonicalization ----------------
__global__ void mask_canon_kernel(const unsigned char* __restrict__ m) {
    __shared__ int offnz, weird;
    if (threadIdx.x == 0) { offnz = 0; weird = 0; }
    __syncthreads();
    for (int i = threadIdx.x; i < 4096; i += 256) {
        unsigned char v = m[i];
        if (v > 1) atomicAdd(&weird, 1);
        else if (v && (i & 3)) atomicAdd(&offnz, 1);
    }
    __syncthreads();
    const int n = B_ * L2_;
    if (weird) {
        const float* f = (const float*)m;
        for (int i = threadIdx.x; i < n; i += 256) g_mask_c[i] = (f[i] != 0.0f) ? 1 : 0;
    } else if (offnz) {
        for (int i = threadIdx.x; i < n; i += 256) g_mask_c[i] = m[i] ? 1 : 0;
    } else {
        const int* mi = (const int*)m;
        for (int i = threadIdx.x; i < n; i += 256) g_mask_c[i] = mi[i] ? 1 : 0;
    }
}

// ---------------- projection GEMM v2 ----------------
// C[16384,1024] = X[16384,1024] @ W[1024,1024] + bias
// Block tile 128(m) x 256(n), k-tile 16, double-buffered via cp.async.
// 8 warps (2m x 4n), warp tile 64x64. Strides: As 20 (≡4 mod 32), Bs 264 (≡8 mod 32)
// keep all fragment LDS bank-conflict-free.
#define PJ_AS 20
#define PJ_BS 264
#define PJ_STAGE (128 * PJ_AS + 16 * PJ_BS)          // 6784 floats
#define PJ_SMEM_BYTES (2 * PJ_STAGE * 4)             // 54272 B

__global__ __launch_bounds__(256, 1)
void proj2_kernel(const float* __restrict__ X, const float* __restrict__ W,
                  const float* __restrict__ bias, float* __restrict__ C) {
    constexpr int N = H_ * DK_;  // 1024
    constexpr int K = DIN_;      // 1024
    extern __shared__ __align__(16) float sm[];

    const int tid  = threadIdx.x;
    const int lane = tid & 31;
    const int warp = tid >> 5;
    const int g  = lane >> 2, tg = lane & 3;
    const int wm = warp >> 2, wn = warp & 3;          // 2 x 4
    const int bm = blockIdx.y * 128, bn = blockIdx.x * 256;

    auto prefetch = [&](int kt, float* stage) {
        float* As = stage;
        float* Bs = stage + 128 * PJ_AS;
#pragma unroll
        for (int i = 0; i < 2; i++) {                  // A: 128x16, 512 chunks
            int c = tid + i * 256;
            int r = c >> 2, q = (c & 3) * 4;
            cpa16(&As[r * PJ_AS + q], &X[(size_t)(bm + r) * K + kt * 16 + q]);
        }
#pragma unroll
        for (int i = 0; i < 4; i++) {                  // B: 16x256, 1024 chunks
            int c = tid + i * 256;
            int kk = c >> 6, n4 = (c & 63) * 4;
            cpa16(&Bs[kk * PJ_BS + n4], &W[(size_t)(kt * 16 + kk) * N + bn + n4]);
        }
    };

    float acc[4][8][4];
#pragma unroll
    for (int i = 0; i < 4; i++)
#pragma unroll
        for (int j = 0; j < 8; j++)
#pragma unroll
            for (int r = 0; r < 4; r++) acc[i][j][r] = 0.f;

    prefetch(0, sm);
    CP_COMMIT();

    for (int kt = 0; kt < K / 16; kt++) {
        if (kt + 1 < K / 16) {
            prefetch(kt + 1, sm + ((kt + 1) & 1) * PJ_STAGE);
            CP_COMMIT();
            CP_WAIT(1);               // tile kt complete, kt+1 in flight
        } else {
            CP_WAIT(0);
        }
        __syncthreads();

        float* As = sm + (kt & 1) * PJ_STAGE;
        float* Bs = As + 128 * PJ_AS;
#pragma unroll
        for (int ks = 0; ks < 2; ks++) {
            unsigned a[4][4];
            int c = ks * 8 + tg;
#pragma unroll
            for (int mt = 0; mt < 4; mt++) {
                int m0 = wm * 64 + mt * 16;
                a[mt][0] = f2tf(As[(m0 + g) * PJ_AS + c]);
                a[mt][1] = f2tf(As[(m0 + g + 8) * PJ_AS + c]);
                a[mt][2] = f2tf(As[(m0 + g) * PJ_AS + c + 4]);
                a[mt][3] = f2tf(As[(m0 + g + 8) * PJ_AS + c + 4]);
            }
#pragma unroll
            for (int nt = 0; nt < 8; nt++) {
                int n0 = wn * 64 + nt * 8 + g;
                unsigned b0 = f2tf(Bs[(ks * 8 + tg) * PJ_BS + n0]);
                unsigned b1 = f2tf(Bs[(ks * 8 + tg + 4) * PJ_BS + n0]);
#pragma unroll
                for (int mt = 0; mt < 4; mt++)
                    mma8(acc[mt][nt], a[mt], b0, b1);
            }
        }
        __syncthreads();              // all warps done before stage is overwritten
    }

    // epilogue: + bias
#pragma unroll
    for (int mt = 0; mt < 4; mt++) {
        int r0 = bm + wm * 64 + mt * 16 + g;
#pragma unroll
        for (int nt = 0; nt < 8; nt++) {
            int cc = bn + wn * 64 + nt * 8 + 2 * tg;
            float b0 = bias[cc], b1 = bias[cc + 1];
            *(float2*)&C[(size_t)r0 * N + cc]       = make_float2(acc[mt][nt][0] + b0, acc[mt][nt][1] + b1);
            *(float2*)&C[(size_t)(r0 + 8) * N + cc] = make_float2(acc[mt][nt][2] + b0, acc[mt][nt][3] + b1);
        }
    }
}

// ---------------- flash attention v2 ----------------
// Grid (L1/256, H, B). 256 threads = 8 warps; warp w owns q rows [w*32, w*32+32)
// (2 m-tiles of 16). kv-tile = 64. Q and P live in SMEM (stride 68), K stride 68,
// V stride 72 -> every fragment LDS is bank-conflict-free. K/V B-fragments are
// shared across the 2 m-tiles, halving per-FLOP smem traffic vs v1.
#define AQS 68
#define APS 68
#define AKS 68
#define AVS 72
#define ATTN_SMEM_FLOATS (256 * AQS + 256 * APS + 64 * AKS + 64 * AVS + 64)
#define ATTN_SMEM_BYTES  (ATTN_SMEM_FLOATS * 4)      // 175,360 B

__global__ __launch_bounds__(256, 1)
void attn2_kernel(const float* __restrict__ Qm, const float* __restrict__ Km,
                  const float* __restrict__ Vm, float* __restrict__ Out) {
    extern __shared__ __align__(16) float sm[];
    float* Qs   = sm;                      // [256][68]
    float* Ps   = Qs + 256 * AQS;          // [256][68]
    float* Ks   = Ps + 256 * APS;          // [64][68]
    float* Vs   = Ks + 64 * AKS;           // [64][72]
    float* mAdd = Vs + 64 * AVS;           // [64]

    const int tid  = threadIdx.x;
    const int lane = tid & 31;
    const int warp = tid >> 5;
    const int g  = lane >> 2, tg = lane & 3;
    const int b  = blockIdx.z, h = blockIdx.y, q0 = blockIdx.x * 256;

    // ---- fill Q tile (256x64), convert to tf32 ----
    {
        const float* qb = Qm + (size_t)(b * L1_ + q0) * (H_ * DK_) + h * DK_;
#pragma unroll
        for (int i = 0; i < 16; i++) {
            int f = tid + i * 256;              // 0..4095
            int r = f >> 4, dq = (f & 15) * 4;
            float4 qv = *(const float4*)&qb[(size_t)r * (H_ * DK_) + dq];
            *(float4*)&Qs[(size_t)r * AQS + dq] =
                make_float4(f2tf_f(qv.x), f2tf_f(qv.y), f2tf_f(qv.z), f2tf_f(qv.w));
        }
    }

    float oacc[2][8][4];
#pragma unroll
    for (int mt = 0; mt < 2; mt++)
#pragma unroll
        for (int i = 0; i < 8; i++)
#pragma unroll
            for (int r = 0; r < 4; r++) oacc[mt][i][r] = 0.f;
    float mrow[2][2] = {{-1e30f, -1e30f}, {-1e30f, -1e30f}};
    float lrow[2][2] = {{0.f, 0.f}, {0.f, 0.f}};

    for (int jt = 0; jt < L2_ / 64; jt++) {
        const int j0 = jt * 64;
        __syncthreads();   // prior iter's K/V reads done (also orders Qs fill at jt=0)
        // ---- fill K,V tiles (64x64 each), convert to tf32 ----
        {
            const float* kb = Km + (size_t)(b * L2_ + j0) * (H_ * DK_) + h * DK_;
            const float* vb = Vm + (size_t)(b * L2_ + j0) * (H_ * DV_) + h * DV_;
#pragma unroll
            for (int i = 0; i < 4; i++) {
                int f = tid + i * 256;          // 0..1023
                int r = f >> 4, dq = (f & 15) * 4;
                float4 kv = *(const float4*)&kb[(size_t)r * (H_ * DK_) + dq];
                float4 vv = *(const float4*)&vb[(size_t)r * (H_ * DV_) + dq];
                *(float4*)&Ks[(size_t)r * AKS + dq] =
                    make_float4(f2tf_f(kv.x), f2tf_f(kv.y), f2tf_f(kv.z), f2tf_f(kv.w));
                *(float4*)&Vs[(size_t)r * AVS + dq] =
                    make_float4(f2tf_f(vv.x), f2tf_f(vv.y), f2tf_f(vv.z), f2tf_f(vv.w));
            }
            if (tid < 64) mAdd[tid] = g_mask_c[b * L2_ + j0 + tid] ? -1e30f : 0.f;
        }
        __syncthreads();

        // ---- S = Q @ K^T : warp computes 32x64 scores ----
        float sacc[2][8][4];
#pragma unroll
        for (int mt = 0; mt < 2; mt++)
#pragma unroll
            for (int nt = 0; nt < 8; nt++)
#pragma unroll
                for (int r = 0; r < 4; r++) sacc[mt][nt][r] = 0.f;
#pragma unroll
        for (int kk = 0; kk < 8; kk++) {
            unsigned qa[2][4];
            int c = kk * 8 + tg;
#pragma unroll
            for (int mt = 0; mt < 2; mt++) {
                int row0 = warp * 32 + mt * 16 + g;
                qa[mt][0] = __float_as_uint(Qs[(size_t)row0 * AQS + c]);
                qa[mt][1] = __float_as_uint(Qs[(size_t)(row0 + 8) * AQS + c]);
                qa[mt][2] = __float_as_uint(Qs[(size_t)row0 * AQS + c + 4]);
                qa[mt][3] = __float_as_uint(Qs[(size_t)(row0 + 8) * AQS + c + 4]);
            }
#pragma unroll
            for (int nt = 0; nt < 8; nt++) {
                unsigned b0 = __float_as_uint(Ks[(size_t)(nt * 8 + g) * AKS + c]);
                unsigned b1 = __float_as_uint(Ks[(size_t)(nt * 8 + g) * AKS + c + 4]);
                mma8(sacc[0][nt], qa[0], b0, b1);
                mma8(sacc[1][nt], qa[1], b0, b1);
            }
        }

        // ---- scale + mask + online softmax (per m-tile) ----
#pragma unroll
        for (int mt = 0; mt < 2; mt++) {
            float tm0 = -1e30f, tm1 = -1e30f;
#pragma unroll
            for (int nt = 0; nt < 8; nt++) {
                int c0 = nt * 8 + 2 * tg;
                float ma = mAdd[c0], mb = mAdd[c0 + 1];
                sacc[mt][nt][0] = sacc[mt][nt][0] * 0.125f + ma;
                sacc[mt][nt][1] = sacc[mt][nt][1] * 0.125f + mb;
                sacc[mt][nt][2] = sacc[mt][nt][2] * 0.125f + ma;
                sacc[mt][nt][3] = sacc[mt][nt][3] * 0.125f + mb;
                tm0 = fmaxf(tm0, fmaxf(sacc[mt][nt][0], sacc[mt][nt][1]));
                tm1 = fmaxf(tm1, fmaxf(sacc[mt][nt][2], sacc[mt][nt][3]));
            }
            tm0 = fmaxf(tm0, __shfl_xor_sync(0xffffffffu, tm0, 1));
            tm0 = fmaxf(tm0, __shfl_xor_sync(0xffffffffu, tm0, 2));
            tm1 = fmaxf(tm1, __shfl_xor_sync(0xffffffffu, tm1, 1));
            tm1 = fmaxf(tm1, __shfl_xor_sync(0xffffffffu, tm1, 2));

            float mn0 = fmaxf(mrow[mt][0], tm0), mn1 = fmaxf(mrow[mt][1], tm1);
            float sc0 = __expf(mrow[mt][0] - mn0), sc1 = __expf(mrow[mt][1] - mn1);
            mrow[mt][0] = mn0; mrow[mt][1] = mn1;
            lrow[mt][0] *= sc0; lrow[mt][1] *= sc1;
#pragma unroll
            for (int nt = 0; nt < 8; nt++) {
                oacc[mt][nt][0] *= sc0; oacc[mt][nt][1] *= sc0;
                oacc[mt][nt][2] *= sc1; oacc[mt][nt][3] *= sc1;
            }
            float* prow0 = &Ps[(size_t)(warp * 32 + mt * 16 + g) * APS];
            float* prow1 = prow0 + (size_t)8 * APS;
#pragma unroll
            for (int nt = 0; nt < 8; nt++) {
                int c0 = nt * 8 + 2 * tg;
                float p0 = (sacc[mt][nt][0] > -1e29f) ? __expf(sacc[mt][nt][0] - mn0) : 0.f;
                float p1 = (sacc[mt][nt][1] > -1e29f) ? __expf(sacc[mt][nt][1] - mn0) : 0.f;
                float p2 = (sacc[mt][nt][2] > -1e29f) ? __expf(sacc[mt][nt][2] - mn1) : 0.f;
                float p3 = (sacc[mt][nt][3] > -1e29f) ? __expf(sacc[mt][nt][3] - mn1) : 0.f;
                lrow[mt][0] += p0 + p1;
                lrow[mt][1] += p2 + p3;
                *(float2*)&prow0[c0] = make_float2(f2tf_f(p0), f2tf_f(p1));
                *(float2*)&prow1[c0] = make_float2(f2tf_f(p2), f2tf_f(p3));
            }
        }
        __syncwarp();      // Ps rows are per-warp private; intra-warp RAW only

        // ---- O += P @ V ----
#pragma unroll
        for (int kk = 0; kk < 8; kk++) {
            unsigned pa[2][4];
            int c = kk * 8 + tg;
#pragma unroll
            for (int mt = 0; mt < 2; mt++) {
                int row0 = warp * 32 + mt * 16 + g;
                pa[mt][0] = __float_as_uint(Ps[(size_t)row0 * APS + c]);
                pa[mt][1] = __float_as_uint(Ps[(size_t)(row0 + 8) * APS + c]);
                pa[mt][2] = __float_as_uint(Ps[(size_t)row0 * APS + c + 4]);
                pa[mt][3] = __float_as_uint(Ps[(size_t)(row0 + 8) * APS + c + 4]);
            }
#pragma unroll
            for (int nt = 0; nt < 8; nt++) {
                unsigned b0 = __float_as_uint(Vs[(size_t)(kk * 8 + tg) * AVS + nt * 8 + g]);
                unsigned b1 = __float_as_uint(Vs[(size_t)(kk * 8 + tg + 4) * AVS + nt * 8 + g]);
                mma8(oacc[0][nt], pa[0], b0, b1);
                mma8(oacc[1][nt], pa[1], b0, b1);
            }
        }
    }

    // ---- finalize ----
#pragma unroll
    for (int mt = 0; mt < 2; mt++) {
        float l0 = lrow[mt][0], l1 = lrow[mt][1];
        l0 += __shfl_xor_sync(0xffffffffu, l0, 1);
        l0 += __shfl_xor_sync(0xffffffffu, l0, 2);
        l1 += __shfl_xor_sync(0xffffffffu, l1, 1);
        l1 += __shfl_xor_sync(0xffffffffu, l1, 2);
        float r0 = 1.f / l0, r1 = 1.f / l1;

        size_t orow0 = (size_t)(b * L1_ + q0 + warp * 32 + mt * 16 + g) * (H_ * DV_) + h * DV_;
        size_t orow1 = orow0 + (size_t)8 * (H_ * DV_);
#pragma unroll
        for (int nt = 0; nt < 8; nt++) {
            int cc = nt * 8 + 2 * tg;
            *(float2*)&Out[orow0 + cc] = make_float2(oacc[mt][nt][0] * r0, oacc[mt][nt][1] * r0);
            *(float2*)&Out[orow1 + cc] = make_float2(oacc[mt][nt][2] * r1, oacc[mt][nt][3] * r1);
        }
    }
}

// ---------------- launch ----------------
extern "C" void kernel_launch(void* const* d_in, const int* in_sizes, int n_in,
                              void* d_out, int out_size) {
    const float* x  = (const float*)d_in[0];
    const float* y  = (const float*)d_in[1];
    const unsigned char* ymask = (const unsigned char*)d_in[2];
    const float* Wq = (const float*)d_in[3];
    const float* bq = (const float*)d_in[4];
    const float* Wk = (const float*)d_in[5];
    const float* bk = (const float*)d_in[6];
    const float* Wv = (const float*)d_in[7];
    const float* bv = (const float*)d_in[8];
    float* out = (float*)d_out;

    float *Qp, *Kp, *Vp;
    cudaGetSymbolAddress((void**)&Qp, g_Q);
    cudaGetSymbolAddress((void**)&Kp, g_K);
    cudaGetSymbolAddress((void**)&Vp, g_V);

    cudaFuncSetAttribute(proj2_kernel, cudaFuncAttributeMaxDynamicSharedMemorySize, PJ_SMEM_BYTES);
    cudaFuncSetAttribute(attn2_kernel, cudaFuncAttributeMaxDynamicSharedMemorySize, ATTN_SMEM_BYTES);

    mask_canon_kernel<<<1, 256>>>(ymask);

    dim3 pgrid(4, 128);  // (N/256, M/128)
    proj2_kernel<<<pgrid, 256, PJ_SMEM_BYTES>>>(x, Wq, bq, Qp);
    proj2_kernel<<<pgrid, 256, PJ_SMEM_BYTES>>>(y, Wk, bk, Kp);
    proj2_kernel<<<pgrid, 256, PJ_SMEM_BYTES>>>(y, Wv, bv, Vp);

    attn2_kernel<<<dim3(L1_ / 256, H_, B_), 256, ATTN_SMEM_BYTES>>>(Qp, Kp, Vp, out);
}

// round 8
// speedup vs baseline: 1.5828x; 1.5828x over previous
#include <cuda_runtime.h>
#include <cuda_fp16.h>
#include <cstdint>

#define B_   16
#define L1_  1024
#define L2_  1024
#define DIN_ 1024
#define H_   16
#define DK_  64
#define DV_  64

// ---------------- scratch (__device__ globals; allocation-free rule) ----------------
// fp16 payloads stored as ushort arrays (avoids __half static-init issues).
__device__ __align__(16) unsigned short g_Qh[B_ * L1_ * H_ * DK_];   // 32 MB
__device__ __align__(16) unsigned short g_Kh[B_ * L2_ * H_ * DK_];   // 32 MB
__device__ __align__(16) unsigned short g_Vh[B_ * L2_ * H_ * DV_];   // 32 MB
__device__ __align__(16) unsigned short g_Xh[B_ * L1_ * DIN_];       // 32 MB
__device__ __align__(16) unsigned short g_Yh[B_ * L2_ * DIN_];       // 32 MB
__device__ __align__(16) unsigned short g_Wth[3][DIN_ * H_ * DK_];   // 6 MB, W^T [N][K]
__device__ unsigned char g_mask_c[B_ * L2_];                         // 1 = masked

// ---------------- helpers ----------------
__device__ __forceinline__ unsigned packh2(float lo, float hi) {
    unsigned r;
    asm("cvt.rn.f16x2.f32 %0, %1, %2;" : "=r"(r) : "f"(hi), "f"(lo));  // hi in high half
    return r;
}

// D(16x8,f32) += A(16x16,f16) * B(16x8,f16)
__device__ __forceinline__ void mma16(float* d, const unsigned* a, unsigned b0, unsigned b1) {
    asm volatile(
        "mma.sync.aligned.m16n8k16.row.col.f32.f16.f16.f32 "
        "{%0,%1,%2,%3}, {%4,%5,%6,%7}, {%8,%9}, {%0,%1,%2,%3};\n"
        : "+f"(d[0]), "+f"(d[1]), "+f"(d[2]), "+f"(d[3])
        : "r"(a[0]), "r"(a[1]), "r"(a[2]), "r"(a[3]), "r"(b0), "r"(b1));
}

__device__ __forceinline__ void cpa16(void* smem, const void* g) {
    unsigned s = (unsigned)__cvta_generic_to_shared(smem);
    asm volatile("cp.async.cg.shared.global [%0], [%1], 16;\n" :: "r"(s), "l"(g));
}
#define CP_COMMIT() asm volatile("cp.async.commit_group;\n" ::: "memory")
#define CP_WAIT(N)  asm volatile("cp.async.wait_group %0;\n" :: "n"(N) : "memory")

// ---------------- mask canonicalization (u8 / i32 / f32 auto-detect) ----------------
__global__ void mask_canon_kernel(const unsigned char* __restrict__ m) {
    __shared__ int offnz, weird;
    if (threadIdx.x == 0) { offnz = 0; weird = 0; }
    __syncthreads();
    for (int i = threadIdx.x; i < 4096; i += 256) {
        unsigned char v = m[i];
        if (v > 1) atomicAdd(&weird, 1);
        else if (v && (i & 3)) atomicAdd(&offnz, 1);
    }
    __syncthreads();
    const int n = B_ * L2_;
    if (weird) {
        const float* f = (const float*)m;
        for (int i = threadIdx.x; i < n; i += 256) g_mask_c[i] = (f[i] != 0.0f) ? 1 : 0;
    } else if (offnz) {
        for (int i = threadIdx.x; i < n; i += 256) g_mask_c[i] = m[i] ? 1 : 0;
    } else {
        const int* mi = (const int*)m;
        for (int i = threadIdx.x; i < n; i += 256) g_mask_c[i] = mi[i] ? 1 : 0;
    }
}

// ---------------- prep: f32 -> f16 (8 elems/thread) ----------------
__global__ void conv_f16_kernel(const float* __restrict__ in, unsigned short* __restrict__ out) {
    size_t i = ((size_t)blockIdx.x * blockDim.x + threadIdx.x) * 8;
    float4 v0 = *(const float4*)&in[i];
    float4 v1 = *(const float4*)&in[i + 4];
    uint4 o;
    o.x = packh2(v0.x, v0.y); o.y = packh2(v0.z, v0.w);
    o.z = packh2(v1.x, v1.y); o.w = packh2(v1.z, v1.w);
    *(uint4*)&out[i] = o;
}

// ---------------- prep: W[K,N] -> Wt[N,K] f16 ----------------
__global__ void wtrans_kernel(const float* __restrict__ W, unsigned short* __restrict__ Wt) {
    __shared__ float t[32][33];
    const int n0 = blockIdx.x * 32, k0 = blockIdx.y * 32;
    const int tx = threadIdx.x, ty = threadIdx.y;   // 32 x 8
#pragma unroll
    for (int i = 0; i < 4; i++)
        t[ty + i * 8][tx] = W[(size_t)(k0 + ty + i * 8) * (H_ * DK_) + n0 + tx];
    __syncthreads();
#pragma unroll
    for (int i = 0; i < 4; i++) {
        __half h = __float2half_rn(t[tx][ty + i * 8]);
        Wt[(size_t)(n0 + ty + i * 8) * DIN_ + k0 + tx] = *(unsigned short*)&h;
    }
}

// ---------------- projection GEMM v4: fp16 m16n8k16 ----------------
// C[16384,1024](f16) = Xh @ Wth^T + bias. CTA tile 64(m) x 256(n), k-tile 32,
// cp.async double-buffered. 8 warps (2m x 4n), warp tile 32x64.
// Half strides 40 (80B = 20 words): all fragment LDS conflict-free.
#define PJ_AS 40
#define PJ_BS 40
#define PJ_STAGE_H (64 * PJ_AS + 256 * PJ_BS)        // halves: 2560 + 10240
#define PJ_SMEM_BYTES (2 * PJ_STAGE_H * 2)           // 51200 B

__global__ __launch_bounds__(256, 2)
void proj4_kernel(const unsigned short* __restrict__ X, const unsigned short* __restrict__ Wt,
                  const float* __restrict__ bias, unsigned short* __restrict__ C) {
    constexpr int N = H_ * DK_;  // 1024
    constexpr int K = DIN_;
    extern __shared__ __align__(16) unsigned short smh[];

    const int tid  = threadIdx.x;
    const int lane = tid & 31;
    const int warp = tid >> 5;
    const int g  = lane >> 2, tg = lane & 3;
    const int wm = warp >> 2, wn = warp & 3;          // 2 x 4
    const int bm = blockIdx.y * 64, bn = blockIdx.x * 256;

    auto prefetch = [&](int kt, int s) {
        unsigned short* As = smh + s * PJ_STAGE_H;
        unsigned short* Bs = As + 64 * PJ_AS;
        {   // A: 64 rows x 32 halves = 256 chunks of 8 halves
            int r = tid >> 2, c = tid & 3;
            cpa16(&As[r * PJ_AS + c * 8], &X[(size_t)(bm + r) * K + kt * 32 + c * 8]);
        }
#pragma unroll
        for (int i = 0; i < 4; i++) {   // B: 256 rows x 32 halves = 1024 chunks
            int f = tid + i * 256;
            int r = f >> 2, c = f & 3;
            cpa16(&Bs[r * PJ_BS + c * 8], &Wt[(size_t)(bn + r) * K + kt * 32 + c * 8]);
        }
        CP_COMMIT();
    };

    float acc[2][8][4];
#pragma unroll
    for (int i = 0; i < 2; i++)
#pragma unroll
        for (int j = 0; j < 8; j++)
#pragma unroll
            for (int r = 0; r < 4; r++) acc[i][j][r] = 0.f;

    prefetch(0, 0);

    for (int kt = 0; kt < K / 32; kt++) {
        const int s = kt & 1;
        if (kt + 1 < K / 32) { prefetch(kt + 1, s ^ 1); CP_WAIT(1); }
        else                 { CP_WAIT(0); }
        __syncthreads();

        const unsigned short* As = smh + s * PJ_STAGE_H;
        const unsigned short* Bs = As + 64 * PJ_AS;
#pragma unroll
        for (int ks = 0; ks < 2; ks++) {
            const int c = 2 * tg + 16 * ks;
            unsigned a[2][4];
#pragma unroll
            for (int mt = 0; mt < 2; mt++) {
                int m0 = wm * 32 + mt * 16;
                a[mt][0] = *(const unsigned*)&As[(m0 + g) * PJ_AS + c];
                a[mt][1] = *(const unsigned*)&As[(m0 + g + 8) * PJ_AS + c];
                a[mt][2] = *(const unsigned*)&As[(m0 + g) * PJ_AS + c + 8];
                a[mt][3] = *(const unsigned*)&As[(m0 + g + 8) * PJ_AS + c + 8];
            }
#pragma unroll
            for (int nt = 0; nt < 8; nt++) {
                int n0 = wn * 64 + nt * 8 + g;
                unsigned b0 = *(const unsigned*)&Bs[n0 * PJ_BS + c];
                unsigned b1 = *(const unsigned*)&Bs[n0 * PJ_BS + c + 8];
                mma16(acc[0][nt], a[0], b0, b1);
                mma16(acc[1][nt], a[1], b0, b1);
            }
        }
        __syncthreads();
    }

    // epilogue: + bias, pack f16
#pragma unroll
    for (int mt = 0; mt < 2; mt++) {
        int r0 = bm + wm * 32 + mt * 16 + g;
#pragma unroll
        for (int nt = 0; nt < 8; nt++) {
            int cc = bn + wn * 64 + nt * 8 + 2 * tg;
            float b0 = bias[cc], b1 = bias[cc + 1];
            *(unsigned*)&C[(size_t)r0 * N + cc] =
                packh2(acc[mt][nt][0] + b0, acc[mt][nt][1] + b1);
            *(unsigned*)&C[(size_t)(r0 + 8) * N + cc] =
                packh2(acc[mt][nt][2] + b0, acc[mt][nt][3] + b1);
        }
    }
}

// ---------------- flash attention v3: fp16 m16n8k16 ----------------
// Grid (L1/256, H, B). 8 warps; warp w owns q rows [w*32, w*32+32). kv-tile 64.
// Half stride 72 (144B = 36 words) everywhere -> conflict-free fragments.
#define AQS 72
#define APS 72
#define AKS 72
#define AVS 72
#define ATTN_SMEM_H (256 * AQS + 256 * APS + 64 * AKS + 64 * AVS)
#define ATTN_SMEM_BYTES (ATTN_SMEM_H * 2 + 64 * 4)   // + mAdd floats = 92,672 B

__global__ __launch_bounds__(256, 1)
void attn3_kernel(const unsigned short* __restrict__ Qm, const unsigned short* __restrict__ Km,
                  const unsigned short* __restrict__ Vm, float* __restrict__ Out) {
    extern __shared__ __align__(16) unsigned short smh[];
    unsigned short* Qs = smh;                    // [256][72]
    unsigned short* Ps = Qs + 256 * AQS;         // [256][72]
    unsigned short* Ks = Ps + 256 * APS;         // [64][72]
    unsigned short* Vs = Ks + 64 * AKS;          // [64][72]
    float* mAdd = (float*)(Vs + 64 * AVS);       // [64]

    const int tid  = threadIdx.x;
    const int lane = tid & 31;
    const int warp = tid >> 5;
    const int g  = lane >> 2, tg = lane & 3;
    const int b  = blockIdx.z, h = blockIdx.y, q0 = blockIdx.x * 256;

    // ---- fill Q tile (256x64 halves), pure copy ----
    {
        const unsigned short* qb = Qm + (size_t)(b * L1_ + q0) * (H_ * DK_) + h * DK_;
#pragma unroll
        for (int i = 0; i < 8; i++) {
            int f = tid + i * 256;               // 0..2047
            int r = f >> 3, c = f & 7;
            *(uint4*)&Qs[r * AQS + c * 8] = *(const uint4*)&qb[(size_t)r * (H_ * DK_) + c * 8];
        }
    }

    float oacc[2][8][4];
#pragma unroll
    for (int mt = 0; mt < 2; mt++)
#pragma unroll
        for (int i = 0; i < 8; i++)
#pragma unroll
            for (int r = 0; r < 4; r++) oacc[mt][i][r] = 0.f;
    float mrow[2][2] = {{-1e30f, -1e30f}, {-1e30f, -1e30f}};
    float lrow[2][2] = {{0.f, 0.f}, {0.f, 0.f}};

    for (int jt = 0; jt < L2_ / 64; jt++) {
        const int j0 = jt * 64;
        __syncthreads();   // prior iter reads done (also orders Qs fill at jt=0)
        {
            const unsigned short* kb = Km + (size_t)(b * L2_ + j0) * (H_ * DK_) + h * DK_;
            const unsigned short* vb = Vm + (size_t)(b * L2_ + j0) * (H_ * DV_) + h * DV_;
#pragma unroll
            for (int i = 0; i < 2; i++) {
                int f = tid + i * 256;           // 0..511
                int r = f >> 3, c = f & 7;
                *(uint4*)&Ks[r * AKS + c * 8] = *(const uint4*)&kb[(size_t)r * (H_ * DK_) + c * 8];
                *(uint4*)&Vs[r * AVS + c * 8] = *(const uint4*)&vb[(size_t)r * (H_ * DV_) + c * 8];
            }
            if (tid < 64) mAdd[tid] = g_mask_c[b * L2_ + j0 + tid] ? -1e30f : 0.f;
        }
        __syncthreads();

        // ---- S = Q @ K^T : warp computes 32x64 scores ----
        float sacc[2][8][4];
#pragma unroll
        for (int mt = 0; mt < 2; mt++)
#pragma unroll
            for (int nt = 0; nt < 8; nt++)
#pragma unroll
                for (int r = 0; r < 4; r++) sacc[mt][nt][r] = 0.f;
#pragma unroll
        for (int kk = 0; kk < 4; kk++) {
            const int c = 2 * tg + 16 * kk;
            unsigned qa[2][4];
#pragma unroll
            for (int mt = 0; mt < 2; mt++) {
                int row0 = warp * 32 + mt * 16 + g;
                qa[mt][0] = *(const unsigned*)&Qs[row0 * AQS + c];
                qa[mt][1] = *(const unsigned*)&Qs[(row0 + 8) * AQS + c];
                qa[mt][2] = *(const unsigned*)&Qs[row0 * AQS + c + 8];
                qa[mt][3] = *(const unsigned*)&Qs[(row0 + 8) * AQS + c + 8];
            }
#pragma unroll
            for (int nt = 0; nt < 8; nt++) {
                int n = nt * 8 + g;
                unsigned b0 = *(const unsigned*)&Ks[n * AKS + c];
                unsigned b1 = *(const unsigned*)&Ks[n * AKS + c + 8];
                mma16(sacc[0][nt], qa[0], b0, b1);
                mma16(sacc[1][nt], qa[1], b0, b1);
            }
        }

        // ---- scale + mask + online softmax ----
#pragma unroll
        for (int mt = 0; mt < 2; mt++) {
            float tm0 = -1e30f, tm1 = -1e30f;
#pragma unroll
            for (int nt = 0; nt < 8; nt++) {
                int c0 = nt * 8 + 2 * tg;
                float ma = mAdd[c0], mb = mAdd[c0 + 1];
                sacc[mt][nt][0] = sacc[mt][nt][0] * 0.125f + ma;
                sacc[mt][nt][1] = sacc[mt][nt][1] * 0.125f + mb;
                sacc[mt][nt][2] = sacc[mt][nt][2] * 0.125f + ma;
                sacc[mt][nt][3] = sacc[mt][nt][3] * 0.125f + mb;
                tm0 = fmaxf(tm0, fmaxf(sacc[mt][nt][0], sacc[mt][nt][1]));
                tm1 = fmaxf(tm1, fmaxf(sacc[mt][nt][2], sacc[mt][nt][3]));
            }
            tm0 = fmaxf(tm0, __shfl_xor_sync(0xffffffffu, tm0, 1));
            tm0 = fmaxf(tm0, __shfl_xor_sync(0xffffffffu, tm0, 2));
            tm1 = fmaxf(tm1, __shfl_xor_sync(0xffffffffu, tm1, 1));
            tm1 = fmaxf(tm1, __shfl_xor_sync(0xffffffffu, tm1, 2));

            float mn0 = fmaxf(mrow[mt][0], tm0), mn1 = fmaxf(mrow[mt][1], tm1);
            float sc0 = __expf(mrow[mt][0] - mn0), sc1 = __expf(mrow[mt][1] - mn1);
            mrow[mt][0] = mn0; mrow[mt][1] = mn1;
            lrow[mt][0] *= sc0; lrow[mt][1] *= sc1;
#pragma unroll
            for (int nt = 0; nt < 8; nt++) {
                oacc[mt][nt][0] *= sc0; oacc[mt][nt][1] *= sc0;
                oacc[mt][nt][2] *= sc1; oacc[mt][nt][3] *= sc1;
            }
            int row0 = warp * 32 + mt * 16 + g;
#pragma unroll
            for (int nt = 0; nt < 8; nt++) {
                int c0 = nt * 8 + 2 * tg;
                float p0 = (sacc[mt][nt][0] > -1e29f) ? __expf(sacc[mt][nt][0] - mn0) : 0.f;
                float p1 = (sacc[mt][nt][1] > -1e29f) ? __expf(sacc[mt][nt][1] - mn0) : 0.f;
                float p2 = (sacc[mt][nt][2] > -1e29f) ? __expf(sacc[mt][nt][2] - mn1) : 0.f;
                float p3 = (sacc[mt][nt][3] > -1e29f) ? __expf(sacc[mt][nt][3] - mn1) : 0.f;
                lrow[mt][0] += p0 + p1;
                lrow[mt][1] += p2 + p3;
                *(unsigned*)&Ps[row0 * APS + c0]       = packh2(p0, p1);
                *(unsigned*)&Ps[(row0 + 8) * APS + c0] = packh2(p2, p3);
            }
        }
        __syncwarp();      // Ps rows per-warp private; intra-warp RAW only

        // ---- O += P @ V  (V B-frags via paired u16 loads, conflict-free) ----
        const __half* Vh = (const __half*)Vs;
#pragma unroll
        for (int kk = 0; kk < 4; kk++) {
            const int c = 2 * tg + 16 * kk;
            unsigned pa[2][4];
#pragma unroll
            for (int mt = 0; mt < 2; mt++) {
                int row0 = warp * 32 + mt * 16 + g;
                pa[mt][0] = *(const unsigned*)&Ps[row0 * APS + c];
                pa[mt][1] = *(const unsigned*)&Ps[(row0 + 8) * APS + c];
                pa[mt][2] = *(const unsigned*)&Ps[row0 * APS + c + 8];
                pa[mt][3] = *(const unsigned*)&Ps[(row0 + 8) * APS + c + 8];
            }
            const int kr = kk * 16 + 2 * tg;
#pragma unroll
            for (int nt = 0; nt < 8; nt++) {
                int n = nt * 8 + g;
                __half2 v0 = __halves2half2(Vh[(kr)     * AVS + n], Vh[(kr + 1) * AVS + n]);
                __half2 v1 = __halves2half2(Vh[(kr + 8) * AVS + n], Vh[(kr + 9) * AVS + n]);
                unsigned b0 = *(unsigned*)&v0;
                unsigned b1 = *(unsigned*)&v1;
                mma16(oacc[0][nt], pa[0], b0, b1);
                mma16(oacc[1][nt], pa[1], b0, b1);
            }
        }
    }

    // ---- finalize ----
#pragma unroll
    for (int mt = 0; mt < 2; mt++) {
        float l0 = lrow[mt][0], l1 = lrow[mt][1];
        l0 += __shfl_xor_sync(0xffffffffu, l0, 1);
        l0 += __shfl_xor_sync(0xffffffffu, l0, 2);
        l1 += __shfl_xor_sync(0xffffffffu, l1, 1);
        l1 += __shfl_xor_sync(0xffffffffu, l1, 2);
        float r0 = 1.f / l0, r1 = 1.f / l1;

        size_t orow0 = (size_t)(b * L1_ + q0 + warp * 32 + mt * 16 + g) * (H_ * DV_) + h * DV_;
        size_t orow1 = orow0 + (size_t)8 * (H_ * DV_);
#pragma unroll
        for (int nt = 0; nt < 8; nt++) {
            int cc = nt * 8 + 2 * tg;
            *(float2*)&Out[orow0 + cc] = make_float2(oacc[mt][nt][0] * r0, oacc[mt][nt][1] * r0);
            *(float2*)&Out[orow1 + cc] = make_float2(oacc[mt][nt][2] * r1, oacc[mt][nt][3] * r1);
        }
    }
}

// ---------------- launch ----------------
extern "C" void kernel_launch(void* const* d_in, const int* in_sizes, int n_in,
                              void* d_out, int out_size) {
    const float* x  = (const float*)d_in[0];
    const float* y  = (const float*)d_in[1];
    const unsigned char* ymask = (const unsigned char*)d_in[2];
    const float* Wq = (const float*)d_in[3];
    const float* bq = (const float*)d_in[4];
    const float* Wk = (const float*)d_in[5];
    const float* bk = (const float*)d_in[6];
    const float* Wv = (const float*)d_in[7];
    const float* bv = (const float*)d_in[8];
    float* out = (float*)d_out;

    unsigned short *Qp, *Kp, *Vp, *Xh, *Yh, *Wth;
    cudaGetSymbolAddress((void**)&Qp,  g_Qh);
    cudaGetSymbolAddress((void**)&Kp,  g_Kh);
    cudaGetSymbolAddress((void**)&Vp,  g_Vh);
    cudaGetSymbolAddress((void**)&Xh,  g_Xh);
    cudaGetSymbolAddress((void**)&Yh,  g_Yh);
    cudaGetSymbolAddress((void**)&Wth, g_Wth);
    unsigned short* Wt0 = Wth;
    unsigned short* Wt1 = Wth + DIN_ * H_ * DK_;
    unsigned short* Wt2 = Wth + 2 * DIN_ * H_ * DK_;

    cudaFuncSetAttribute(proj4_kernel, cudaFuncAttributeMaxDynamicSharedMemorySize, PJ_SMEM_BYTES);
    cudaFuncSetAttribute(attn3_kernel, cudaFuncAttributeMaxDynamicSharedMemorySize, ATTN_SMEM_BYTES);

    mask_canon_kernel<<<1, 256>>>(ymask);

    conv_f16_kernel<<<(B_ * L1_ * DIN_) / (256 * 8), 256>>>(x, Xh);
    conv_f16_kernel<<<(B_ * L2_ * DIN_) / (256 * 8), 256>>>(y, Yh);
    dim3 tgrid(32, 32), tblk(32, 8);
    wtrans_kernel<<<tgrid, tblk>>>(Wq, Wt0);
    wtrans_kernel<<<tgrid, tblk>>>(Wk, Wt1);
    wtrans_kernel<<<tgrid, tblk>>>(Wv, Wt2);

    dim3 pgrid(H_ * DK_ / 256, (B_ * L1_) / 64);     // (4, 256)
    proj4_kernel<<<pgrid, 256, PJ_SMEM_BYTES>>>(Xh, Wt0, bq, Qp);
    proj4_kernel<<<pgrid, 256, PJ_SMEM_BYTES>>>(Yh, Wt1, bk, Kp);
    proj4_kernel<<<pgrid, 256, PJ_SMEM_BYTES>>>(Yh, Wt2, bv, Vp);

    attn3_kernel<<<dim3(L1_ / 256, H_, B_), 256, ATTN_SMEM_BYTES>>>(Qp, Kp, Vp, out);
}

// round 9
// speedup vs baseline: 2.4261x; 1.5328x over previous
#include <cuda_runtime.h>
#include <cuda_fp16.h>
#include <cstdint>

#define B_   16
#define L1_  1024
#define L2_  1024
#define DIN_ 1024
#define H_   16
#define DK_  64
#define DV_  64

// ---------------- scratch (__device__ globals; allocation-free rule) ----------------
__device__ __align__(16) unsigned short g_Qh[B_ * L1_ * H_ * DK_];   // 32 MB
__device__ __align__(16) unsigned short g_Kh[B_ * L2_ * H_ * DK_];   // 32 MB (compacted)
__device__ __align__(16) unsigned short g_Vh[B_ * L2_ * H_ * DV_];   // 32 MB (compacted)
__device__ __align__(16) unsigned short g_Xh[B_ * L1_ * DIN_];       // 32 MB
__device__ __align__(16) unsigned short g_Yh[B_ * L2_ * DIN_];       // 32 MB
__device__ __align__(16) unsigned short g_Wth[3][DIN_ * H_ * DK_];   // 6 MB, W^T [N][K]
__device__ int g_cnt[B_];                                            // unmasked count per batch
__device__ unsigned short g_idx[B_][L2_];                            // compacted unmasked indices

// ---------------- helpers ----------------
__device__ __forceinline__ unsigned packh2(float lo, float hi) {
    unsigned r;
    asm("cvt.rn.f16x2.f32 %0, %1, %2;" : "=r"(r) : "f"(hi), "f"(lo));  // hi in high half
    return r;
}

__device__ __forceinline__ void mma16(float* d, const unsigned* a, unsigned b0, unsigned b1) {
    asm volatile(
        "mma.sync.aligned.m16n8k16.row.col.f32.f16.f16.f32 "
        "{%0,%1,%2,%3}, {%4,%5,%6,%7}, {%8,%9}, {%0,%1,%2,%3};\n"
        : "+f"(d[0]), "+f"(d[1]), "+f"(d[2]), "+f"(d[3])
        : "r"(a[0]), "r"(a[1]), "r"(a[2]), "r"(a[3]), "r"(b0), "r"(b1));
}

__device__ __forceinline__ void cpa16(void* smem, const void* g) {
    unsigned s = (unsigned)__cvta_generic_to_shared(smem);
    asm volatile("cp.async.cg.shared.global [%0], [%1], 16;\n" :: "r"(s), "l"(g));
}
#define CP_COMMIT() asm volatile("cp.async.commit_group;\n" ::: "memory")
#define CP_WAIT(N)  asm volatile("cp.async.wait_group %0;\n" :: "n"(N) : "memory")

// ---------------- mask canonicalize + compact (one block per batch) ----------------
// Encoding auto-detect (u8 / i32 / f32) from first 4096 bytes, then block-wide
// prefix scan builds the ascending list of unmasked indices for this batch.
__global__ void mask_compact_kernel(const unsigned char* __restrict__ m) {
    __shared__ int offnz, weird;
    __shared__ int cnts[256];
    const int b = blockIdx.x;
    const int tid = threadIdx.x;
    if (tid == 0) { offnz = 0; weird = 0; }
    __syncthreads();
    for (int i = tid; i < 4096; i += 256) {
        unsigned char v = m[i];
        if (v > 1) atomicAdd(&weird, 1);
        else if (v && (i & 3)) atomicAdd(&offnz, 1);
    }
    __syncthreads();
    const int wd = weird, on = offnz;

    int f[4], myc = 0;
#pragma unroll
    for (int j = 0; j < 4; j++) {
        int e = b * L2_ + tid * 4 + j;
        int masked;
        if (wd)      masked = (((const float*)m)[e] != 0.0f);
        else if (on) masked = (m[e] != 0);
        else         masked = (((const int*)m)[e] != 0);
        f[j] = !masked;
        myc += f[j];
    }
    cnts[tid] = myc;
    __syncthreads();
    for (int off = 1; off < 256; off <<= 1) {   // inclusive Hillis-Steele scan
        int v = (tid >= off) ? cnts[tid - off] : 0;
        __syncthreads();
        cnts[tid] += v;
        __syncthreads();
    }
    int pos = cnts[tid] - myc;
#pragma unroll
    for (int j = 0; j < 4; j++)
        if (f[j]) g_idx[b][pos++] = (unsigned short)(tid * 4 + j);
    if (tid == 255) g_cnt[b] = cnts[255];
}

// ---------------- prep: f32 -> f16 (8 elems/thread) ----------------
__global__ void conv_f16_kernel(const float* __restrict__ in, unsigned short* __restrict__ out) {
    size_t i = ((size_t)blockIdx.x * blockDim.x + threadIdx.x) * 8;
    float4 v0 = *(const float4*)&in[i];
    float4 v1 = *(const float4*)&in[i + 4];
    uint4 o;
    o.x = packh2(v0.x, v0.y); o.y = packh2(v0.z, v0.w);
    o.z = packh2(v1.x, v1.y); o.w = packh2(v1.z, v1.w);
    *(uint4*)&out[i] = o;
}

// ---------------- prep: W[K,N] -> Wt[N,K] f16 ----------------
__global__ void wtrans_kernel(const float* __restrict__ W, unsigned short* __restrict__ Wt) {
    __shared__ float t[32][33];
    const int n0 = blockIdx.x * 32, k0 = blockIdx.y * 32;
    const int tx = threadIdx.x, ty = threadIdx.y;   // 32 x 8
#pragma unroll
    for (int i = 0; i < 4; i++)
        t[ty + i * 8][tx] = W[(size_t)(k0 + ty + i * 8) * (H_ * DK_) + n0 + tx];
    __syncthreads();
#pragma unroll
    for (int i = 0; i < 4; i++) {
        __half h = __float2half_rn(t[tx][ty + i * 8]);
        Wt[(size_t)(n0 + ty + i * 8) * DIN_ + k0 + tx] = *(unsigned short*)&h;
    }
}

// ---------------- projection GEMM: fp16 m16n8k16, optional row gather ----------------
// C = X(rows) @ Wt^T + bias. CTA tile 64(m) x 256(n), k-tile 32, cp.async dbuf.
// 8 warps (2m x 4n), warp tile 32x64. Half stride 40: conflict-free fragments.
// GATHER: blockIdx.y = b*16 + tile; processes compacted rows idx[b][tile*64 ..],
// exits early when tile start >= cnt[b]; outputs to compacted row space.
#define PJ_AS 40
#define PJ_BS 40
#define PJ_STAGE_H (64 * PJ_AS + 256 * PJ_BS)
#define PJ_SMEM_BYTES (2 * PJ_STAGE_H * 2)           // 51200 B

template <bool GATHER>
__global__ __launch_bounds__(256, 2)
void proj_kernel_t(const unsigned short* __restrict__ X, const unsigned short* __restrict__ Wt,
                   const float* __restrict__ bias, unsigned short* __restrict__ C) {
    constexpr int N = H_ * DK_;
    constexpr int K = DIN_;
    extern __shared__ __align__(16) unsigned short smh[];

    const int tid  = threadIdx.x;
    const int lane = tid & 31;
    const int warp = tid >> 5;
    const int g  = lane >> 2, tg = lane & 3;
    const int wm = warp >> 2, wn = warp & 3;          // 2 x 4
    const int bn = blockIdx.x * 256;

    int b = 0, bml = 0;
    size_t out_base;
    if (GATHER) {
        b   = blockIdx.y >> 4;
        bml = (blockIdx.y & 15) * 64;
        if (bml >= g_cnt[b]) return;                  // whole-block uniform exit
        out_base = (size_t)(b * L2_ + bml);
    } else {
        out_base = (size_t)blockIdx.y * 64;
    }

    // per-thread A source row (constant across k-tiles)
    const unsigned short* arow;
    {
        int r = tid >> 2;                              // 0..63
        if (GATHER) {
            int jp = bml + r;
            int src = (jp < g_cnt[b]) ? (int)g_idx[b][jp] : (int)g_idx[b][0];
            arow = X + (size_t)(b * L2_ + src) * K;
        } else {
            arow = X + (out_base + r) * K;
        }
    }

    auto prefetch = [&](int kt, int s) {
        unsigned short* As = smh + s * PJ_STAGE_H;
        unsigned short* Bs = As + 64 * PJ_AS;
        {   // A: 64 rows x 32 halves
            int r = tid >> 2, c = tid & 3;
            cpa16(&As[r * PJ_AS + c * 8], arow + kt * 32 + c * 8);
        }
#pragma unroll
        for (int i = 0; i < 4; i++) {                  // B: 256 rows x 32 halves
            int f = tid + i * 256;
            int r = f >> 2, c = f & 3;
            cpa16(&Bs[r * PJ_BS + c * 8], &Wt[(size_t)(bn + r) * K + kt * 32 + c * 8]);
        }
        CP_COMMIT();
    };

    float acc[2][8][4];
#pragma unroll
    for (int i = 0; i < 2; i++)
#pragma unroll
        for (int j = 0; j < 8; j++)
#pragma unroll
            for (int r = 0; r < 4; r++) acc[i][j][r] = 0.f;

    prefetch(0, 0);

    for (int kt = 0; kt < K / 32; kt++) {
        const int s = kt & 1;
        if (kt + 1 < K / 32) { prefetch(kt + 1, s ^ 1); CP_WAIT(1); }
        else                 { CP_WAIT(0); }
        __syncthreads();

        const unsigned short* As = smh + s * PJ_STAGE_H;
        const unsigned short* Bs = As + 64 * PJ_AS;
#pragma unroll
        for (int ks = 0; ks < 2; ks++) {
            const int c = 2 * tg + 16 * ks;
            unsigned a[2][4];
#pragma unroll
            for (int mt = 0; mt < 2; mt++) {
                int m0 = wm * 32 + mt * 16;
                a[mt][0] = *(const unsigned*)&As[(m0 + g) * PJ_AS + c];
                a[mt][1] = *(const unsigned*)&As[(m0 + g + 8) * PJ_AS + c];
                a[mt][2] = *(const unsigned*)&As[(m0 + g) * PJ_AS + c + 8];
                a[mt][3] = *(const unsigned*)&As[(m0 + g + 8) * PJ_AS + c + 8];
            }
#pragma unroll
            for (int nt = 0; nt < 8; nt++) {
                int n0 = wn * 64 + nt * 8 + g;
                unsigned b0 = *(const unsigned*)&Bs[n0 * PJ_BS + c];
                unsigned b1 = *(const unsigned*)&Bs[n0 * PJ_BS + c + 8];
                mma16(acc[0][nt], a[0], b0, b1);
                mma16(acc[1][nt], a[1], b0, b1);
            }
        }
        __syncthreads();
    }

#pragma unroll
    for (int mt = 0; mt < 2; mt++) {
        size_t r0 = out_base + wm * 32 + mt * 16 + g;
#pragma unroll
        for (int nt = 0; nt < 8; nt++) {
            int cc = bn + wn * 64 + nt * 8 + 2 * tg;
            float b0 = bias[cc], b1 = bias[cc + 1];
            *(unsigned*)&C[r0 * N + cc] =
                packh2(acc[mt][nt][0] + b0, acc[mt][nt][1] + b1);
            *(unsigned*)&C[(r0 + 8) * N + cc] =
                packh2(acc[mt][nt][2] + b0, acc[mt][nt][3] + b1);
        }
    }
}

// ---------------- flash attention: fp16 m16n8k16, compacted KV ----------------
// Grid (L1/256, H, B). 8 warps; warp w owns q rows [w*32, w*32+32). kv-tile 64.
// K/V are compacted: only ceil(cnt[b]/64) tiles iterated; tail padded via mAdd.
#define AQS 72
#define APS 72
#define AKS 72
#define AVS 72
#define ATTN_SMEM_H (256 * AQS + 256 * APS + 64 * AKS + 64 * AVS)
#define ATTN_SMEM_BYTES (ATTN_SMEM_H * 2 + 64 * 4)

__global__ __launch_bounds__(256, 1)
void attn3_kernel(const unsigned short* __restrict__ Qm, const unsigned short* __restrict__ Km,
                  const unsigned short* __restrict__ Vm, float* __restrict__ Out) {
    extern __shared__ __align__(16) unsigned short smh[];
    unsigned short* Qs = smh;                    // [256][72]
    unsigned short* Ps = Qs + 256 * AQS;         // [256][72]
    unsigned short* Ks = Ps + 256 * APS;         // [64][72]
    unsigned short* Vs = Ks + 64 * AKS;          // [64][72]
    float* mAdd = (float*)(Vs + 64 * AVS);       // [64]

    const int tid  = threadIdx.x;
    const int lane = tid & 31;
    const int warp = tid >> 5;
    const int g  = lane >> 2, tg = lane & 3;
    const int b  = blockIdx.z, h = blockIdx.y, q0 = blockIdx.x * 256;

    const int cnt    = g_cnt[b];
    const int ntiles = (cnt + 63) >> 6;

    {
        const unsigned short* qb = Qm + (size_t)(b * L1_ + q0) * (H_ * DK_) + h * DK_;
#pragma unroll
        for (int i = 0; i < 8; i++) {
            int f = tid + i * 256;
            int r = f >> 3, c = f & 7;
            *(uint4*)&Qs[r * AQS + c * 8] = *(const uint4*)&qb[(size_t)r * (H_ * DK_) + c * 8];
        }
    }

    float oacc[2][8][4];
#pragma unroll
    for (int mt = 0; mt < 2; mt++)
#pragma unroll
        for (int i = 0; i < 8; i++)
#pragma unroll
            for (int r = 0; r < 4; r++) oacc[mt][i][r] = 0.f;
    float mrow[2][2] = {{-1e30f, -1e30f}, {-1e30f, -1e30f}};
    float lrow[2][2] = {{0.f, 0.f}, {0.f, 0.f}};

    for (int jt = 0; jt < ntiles; jt++) {
        const int j0 = jt * 64;
        __syncthreads();
        {
            const unsigned short* kb = Km + (size_t)(b * L2_ + j0) * (H_ * DK_) + h * DK_;
            const unsigned short* vb = Vm + (size_t)(b * L2_ + j0) * (H_ * DV_) + h * DV_;
#pragma unroll
            for (int i = 0; i < 2; i++) {
                int f = tid + i * 256;
                int r = f >> 3, c = f & 7;
                *(uint4*)&Ks[r * AKS + c * 8] = *(const uint4*)&kb[(size_t)r * (H_ * DK_) + c * 8];
                *(uint4*)&Vs[r * AVS + c * 8] = *(const uint4*)&vb[(size_t)r * (H_ * DV_) + c * 8];
            }
            if (tid < 64) mAdd[tid] = (j0 + tid < cnt) ? 0.f : -1e30f;
        }
        __syncthreads();

        // ---- S = Q @ K^T ----
        float sacc[2][8][4];
#pragma unroll
        for (int mt = 0; mt < 2; mt++)
#pragma unroll
            for (int nt = 0; nt < 8; nt++)
#pragma unroll
                for (int r = 0; r < 4; r++) sacc[mt][nt][r] = 0.f;
#pragma unroll
        for (int kk = 0; kk < 4; kk++) {
            const int c = 2 * tg + 16 * kk;
            unsigned qa[2][4];
#pragma unroll
            for (int mt = 0; mt < 2; mt++) {
                int row0 = warp * 32 + mt * 16 + g;
                qa[mt][0] = *(const unsigned*)&Qs[row0 * AQS + c];
                qa[mt][1] = *(const unsigned*)&Qs[(row0 + 8) * AQS + c];
                qa[mt][2] = *(const unsigned*)&Qs[row0 * AQS + c + 8];
                qa[mt][3] = *(const unsigned*)&Qs[(row0 + 8) * AQS + c + 8];
            }
#pragma unroll
            for (int nt = 0; nt < 8; nt++) {
                int n = nt * 8 + g;
                unsigned b0 = *(const unsigned*)&Ks[n * AKS + c];
                unsigned b1 = *(const unsigned*)&Ks[n * AKS + c + 8];
                mma16(sacc[0][nt], qa[0], b0, b1);
                mma16(sacc[1][nt], qa[1], b0, b1);
            }
        }

        // ---- scale + tail mask + online softmax ----
#pragma unroll
        for (int mt = 0; mt < 2; mt++) {
            float tm0 = -1e30f, tm1 = -1e30f;
#pragma unroll
            for (int nt = 0; nt < 8; nt++) {
                int c0 = nt * 8 + 2 * tg;
                float ma = mAdd[c0], mb = mAdd[c0 + 1];
                sacc[mt][nt][0] = sacc[mt][nt][0] * 0.125f + ma;
                sacc[mt][nt][1] = sacc[mt][nt][1] * 0.125f + mb;
                sacc[mt][nt][2] = sacc[mt][nt][2] * 0.125f + ma;
                sacc[mt][nt][3] = sacc[mt][nt][3] * 0.125f + mb;
                tm0 = fmaxf(tm0, fmaxf(sacc[mt][nt][0], sacc[mt][nt][1]));
                tm1 = fmaxf(tm1, fmaxf(sacc[mt][nt][2], sacc[mt][nt][3]));
            }
            tm0 = fmaxf(tm0, __shfl_xor_sync(0xffffffffu, tm0, 1));
            tm0 = fmaxf(tm0, __shfl_xor_sync(0xffffffffu, tm0, 2));
            tm1 = fmaxf(tm1, __shfl_xor_sync(0xffffffffu, tm1, 1));
            tm1 = fmaxf(tm1, __shfl_xor_sync(0xffffffffu, tm1, 2));

            float mn0 = fmaxf(mrow[mt][0], tm0), mn1 = fmaxf(mrow[mt][1], tm1);
            float sc0 = __expf(mrow[mt][0] - mn0), sc1 = __expf(mrow[mt][1] - mn1);
            mrow[mt][0] = mn0; mrow[mt][1] = mn1;
            lrow[mt][0] *= sc0; lrow[mt][1] *= sc1;
#pragma unroll
            for (int nt = 0; nt < 8; nt++) {
                oacc[mt][nt][0] *= sc0; oacc[mt][nt][1] *= sc0;
                oacc[mt][nt][2] *= sc1; oacc[mt][nt][3] *= sc1;
            }
            int row0 = warp * 32 + mt * 16 + g;
#pragma unroll
            for (int nt = 0; nt < 8; nt++) {
                int c0 = nt * 8 + 2 * tg;
                float p0 = (sacc[mt][nt][0] > -1e29f) ? __expf(sacc[mt][nt][0] - mn0) : 0.f;
                float p1 = (sacc[mt][nt][1] > -1e29f) ? __expf(sacc[mt][nt][1] - mn0) : 0.f;
                float p2 = (sacc[mt][nt][2] > -1e29f) ? __expf(sacc[mt][nt][2] - mn1) : 0.f;
                float p3 = (sacc[mt][nt][3] > -1e29f) ? __expf(sacc[mt][nt][3] - mn1) : 0.f;
                lrow[mt][0] += p0 + p1;
                lrow[mt][1] += p2 + p3;
                *(unsigned*)&Ps[row0 * APS + c0]       = packh2(p0, p1);
                *(unsigned*)&Ps[(row0 + 8) * APS + c0] = packh2(p2, p3);
            }
        }
        __syncwarp();

        // ---- O += P @ V ----
        const __half* Vh = (const __half*)Vs;
#pragma unroll
        for (int kk = 0; kk < 4; kk++) {
            const int c = 2 * tg + 16 * kk;
            unsigned pa[2][4];
#pragma unroll
            for (int mt = 0; mt < 2; mt++) {
                int row0 = warp * 32 + mt * 16 + g;
                pa[mt][0] = *(const unsigned*)&Ps[row0 * APS + c];
                pa[mt][1] = *(const unsigned*)&Ps[(row0 + 8) * APS + c];
                pa[mt][2] = *(const unsigned*)&Ps[row0 * APS + c + 8];
                pa[mt][3] = *(const unsigned*)&Ps[(row0 + 8) * APS + c + 8];
            }
            const int kr = kk * 16 + 2 * tg;
#pragma unroll
            for (int nt = 0; nt < 8; nt++) {
                int n = nt * 8 + g;
                __half2 v0 = __halves2half2(Vh[(kr)     * AVS + n], Vh[(kr + 1) * AVS + n]);
                __half2 v1 = __halves2half2(Vh[(kr + 8) * AVS + n], Vh[(kr + 9) * AVS + n]);
                unsigned b0 = *(unsigned*)&v0;
                unsigned b1 = *(unsigned*)&v1;
                mma16(oacc[0][nt], pa[0], b0, b1);
                mma16(oacc[1][nt], pa[1], b0, b1);
            }
        }
    }

    // ---- finalize ----
#pragma unroll
    for (int mt = 0; mt < 2; mt++) {
        float l0 = lrow[mt][0], l1 = lrow[mt][1];
        l0 += __shfl_xor_sync(0xffffffffu, l0, 1);
        l0 += __shfl_xor_sync(0xffffffffu, l0, 2);
        l1 += __shfl_xor_sync(0xffffffffu, l1, 1);
        l1 += __shfl_xor_sync(0xffffffffu, l1, 2);
        float r0 = 1.f / l0, r1 = 1.f / l1;

        size_t orow0 = (size_t)(b * L1_ + q0 + warp * 32 + mt * 16 + g) * (H_ * DV_) + h * DV_;
        size_t orow1 = orow0 + (size_t)8 * (H_ * DV_);
#pragma unroll
        for (int nt = 0; nt < 8; nt++) {
            int cc = nt * 8 + 2 * tg;
            *(float2*)&Out[orow0 + cc] = make_float2(oacc[mt][nt][0] * r0, oacc[mt][nt][1] * r0);
            *(float2*)&Out[orow1 + cc] = make_float2(oacc[mt][nt][2] * r1, oacc[mt][nt][3] * r1);
        }
    }
}

// ---------------- launch ----------------
extern "C" void kernel_launch(void* const* d_in, const int* in_sizes, int n_in,
                              void* d_out, int out_size) {
    const float* x  = (const float*)d_in[0];
    const float* y  = (const float*)d_in[1];
    const unsigned char* ymask = (const unsigned char*)d_in[2];
    const float* Wq = (const float*)d_in[3];
    const float* bq = (const float*)d_in[4];
    const float* Wk = (const float*)d_in[5];
    const float* bk = (const float*)d_in[6];
    const float* Wv = (const float*)d_in[7];
    const float* bv = (const float*)d_in[8];
    float* out = (float*)d_out;

    unsigned short *Qp, *Kp, *Vp, *Xh, *Yh, *Wth;
    cudaGetSymbolAddress((void**)&Qp,  g_Qh);
    cudaGetSymbolAddress((void**)&Kp,  g_Kh);
    cudaGetSymbolAddress((void**)&Vp,  g_Vh);
    cudaGetSymbolAddress((void**)&Xh,  g_Xh);
    cudaGetSymbolAddress((void**)&Yh,  g_Yh);
    cudaGetSymbolAddress((void**)&Wth, g_Wth);
    unsigned short* Wt0 = Wth;
    unsigned short* Wt1 = Wth + DIN_ * H_ * DK_;
    unsigned short* Wt2 = Wth + 2 * DIN_ * H_ * DK_;

    cudaFuncSetAttribute(proj_kernel_t<false>, cudaFuncAttributeMaxDynamicSharedMemorySize, PJ_SMEM_BYTES);
    cudaFuncSetAttribute(proj_kernel_t<true>,  cudaFuncAttributeMaxDynamicSharedMemorySize, PJ_SMEM_BYTES);
    cudaFuncSetAttribute(attn3_kernel, cudaFuncAttributeMaxDynamicSharedMemorySize, ATTN_SMEM_BYTES);

    mask_compact_kernel<<<B_, 256>>>(ymask);

    conv_f16_kernel<<<(B_ * L1_ * DIN_) / (256 * 8), 256>>>(x, Xh);
    conv_f16_kernel<<<(B_ * L2_ * DIN_) / (256 * 8), 256>>>(y, Yh);
    dim3 tgrid(32, 32), tblk(32, 8);
    wtrans_kernel<<<tgrid, tblk>>>(Wq, Wt0);
    wtrans_kernel<<<tgrid, tblk>>>(Wk, Wt1);
    wtrans_kernel<<<tgrid, tblk>>>(Wv, Wt2);

    // Q over all x rows; K/V only over unmasked (compacted) y rows
    proj_kernel_t<false><<<dim3(4, 256), 256, PJ_SMEM_BYTES>>>(Xh, Wt0, bq, Qp);
    proj_kernel_t<true><<<dim3(4, B_ * 16), 256, PJ_SMEM_BYTES>>>(Yh, Wt1, bk, Kp);
    proj_kernel_t<true><<<dim3(4, B_ * 16), 256, PJ_SMEM_BYTES>>>(Yh, Wt2, bv, Vp);

    attn3_kernel<<<dim3(L1_ / 256, H_, B_), 256, ATTN_SMEM_BYTES>>>(Qp, Kp, Vp, out);
}